// round 5
// baseline (speedup 1.0000x reference)
#include <cuda_runtime.h>
#include <math_constants.h>

// ---------------------------------------------------------------------------
// IttiKochSaliency, x[8,3,512,512] -> out[8,512,512]
//
// Identities:
//  * pipeline invariant under positive affine input transforms -> reference's
//    input normalization dropped.
//  * bilinear resize & channel-mean are linear -> channels pre-combined into
//    one QUAD-DUP float4 map per (b,level): k_final = 7 LDG.128 per pixel.
//  * per-map scales/offsets are 168 scalars -> recomputed inline (no k_scale).
//
// Launches (6):
//  k_pyr<0..2> : separable 6-tap [1,5,10,10,5,1]/32 stride-2 reflect filter
//                (== 5x5 binomial + bilinear half-resize), float2 loads
//  k_mid       : blocks <24 FIRST: per-(b,c) tail — pyramid 64->2 + diffs
//                i=2..6 in smem (template-unrolled stages), stats direct;
//                blocks >=24: diffs i=0,1 as 32x16 regions, stats via atomics
//  k_comb      : per (b,i): quad-dup float4 of sum_c s_bc*d_bc (smem tile)
//  k_final     : 7-level bilinear gather, 1 LDG.128 per level per pixel
//
// R4 bug fixed here: k_comb dispatch table was one entry short, so level i=6
// got zero blocks (g_q stayed zero) -> rel_err 0.446. Table now has 8 edges
// and the grid is 2744.
// ---------------------------------------------------------------------------

__device__ float    g_pyr[2064384];   // pyr levels 0..2 (h=256,128,64) per bc
__device__ float    g_d[2097024];     // diff maps i=0..6 per bc
__device__ float4   g_q[699008];      // quad-dup combined maps per (b,i)
__device__ unsigned g_dmn[168], g_dmx[168];
__device__ float    g_tsum[168];

__constant__ int c_off[8] = {0, 1572864, 1966080, 2064384,
                             2088960, 2095104, 2096640, 2097024};
__constant__ int co2[7]  = {0, 524288, 655360, 688128, 696320, 698368, 698880};
__constant__ int cb[8]   = {0, 2048, 2560, 2688, 2720, 2728, 2736, 2744};

__device__ __forceinline__ int refl(int t, int n) {
    return t < 0 ? -t : (t >= n ? 2 * n - 2 - t : t);
}
__device__ __forceinline__ unsigned fenc(float f) {
    unsigned u = __float_as_uint(f);
    return (u & 0x80000000u) ? ~u : (u | 0x80000000u);
}
__device__ __forceinline__ float fdec(unsigned u) {
    return __uint_as_float((u & 0x80000000u) ? (u ^ 0x80000000u) : ~u);
}
// scale for one (b,c,i) stat triple; includes the 1/3 channel-mean factor
__device__ __forceinline__ float calc_scale(int sidx, int i, float* mn_out) {
    float mn = fdec(g_dmn[sidx]), mx = fdec(g_dmx[sidx]);
    float inv = 1.f / (mx - mn);
    int n = (16 >> i) - 1;
    float lm = (n > 0) ? (g_tsum[sidx] / (float)(n * n) - mn) * inv : 0.f;
    float om = 1.f - lm;
    *mn_out = mn;
    return om * om * inv * (1.f / 3.f);
}

#define W0 0.03125f
#define W1 0.15625f
#define W2 0.3125f

// ---------------- separable pyrdown: HI -> HI/2, 32x16 output tile ----------
template <int LVL>
__global__ void __launch_bounds__(512) k_pyr(const float* __restrict__ x) {
    constexpr int HI = 512 >> LVL, HO = HI / 2;
    __shared__ float s_in[36 * 68];
    __shared__ float s_h[36 * 32];
    const int t = threadIdx.x;
    if (LVL == 0 && blockIdx.x == 0 && blockIdx.y == 0 && blockIdx.z == 0 && t < 168) {
        g_dmn[t] = 0xFFFFFFFFu; g_dmx[t] = 0u; g_tsum[t] = 0.f;
    }
    const int bc = blockIdx.z;
    const int ox0 = blockIdx.x * 32, oy0 = blockIdx.y * 16;
    const float* in = (LVL == 0) ? (x + (size_t)bc * HI * HI)
                                 : (g_pyr + c_off[LVL - 1] + (size_t)bc * HI * HI);
    float* out = g_pyr + c_off[LVL] + (size_t)bc * HO * HO;
    const int iy0 = 2 * oy0 - 2, ix0 = 2 * ox0 - 2;
    for (int idx = t; idx < 36 * 34; idx += 512) {
        int r = idx / 34, c2 = idx - r * 34;
        int gy = refl(iy0 + r, HI);
        int ix = ix0 + 2 * c2;
        float v0, v1;
        if (ix >= 0 && ix + 2 <= HI) {
            float2 p = *(const float2*)(in + gy * HI + ix);
            v0 = p.x; v1 = p.y;
        } else {
            v0 = in[gy * HI + refl(ix, HI)];
            v1 = in[gy * HI + refl(ix + 1, HI)];
        }
        s_in[r * 68 + 2 * c2]     = v0;
        s_in[r * 68 + 2 * c2 + 1] = v1;
    }
    __syncthreads();
    for (int idx = t; idx < 36 * 32; idx += 512) {
        int r = idx >> 5, c = idx & 31;
        const float* p = s_in + r * 68 + 2 * c;
        s_h[idx] = W0 * (p[0] + p[5]) + W1 * (p[1] + p[4]) + W2 * (p[2] + p[3]);
    }
    __syncthreads();
    const int tx = t & 31, ty = t >> 5;
    const float* q = s_h + 2 * ty * 32 + tx;
    float acc = W0 * (q[0] + q[160]) + W1 * (q[32] + q[128]) + W2 * (q[64] + q[96]);
    out[(oy0 + ty) * HO + ox0 + tx] = acc;
}

// ---------------- tail stage (compile-time size) ------------------------------
template <int LGF>
__device__ __forceinline__ void tail_stage(int t, int bc, float* F, float* C,
                                           float* Hs, float* wmn, float* wmx,
                                           float* stile) {
    constexpr int HF = 1 << LGF, HC = HF >> 1, I = 8 - LGF;
    for (int idx = t; idx < HF * HC; idx += 512) {
        int r = idx >> (LGF - 1), c = idx & (HC - 1);
        const float* row = F + (r << LGF);
        int c0 = 2 * c;
        Hs[idx] = W0 * (row[refl(c0 - 2, HF)] + row[refl(c0 + 3, HF)])
                + W1 * (row[refl(c0 - 1, HF)] + row[refl(c0 + 2, HF)])
                + W2 * (row[c0] + row[c0 + 1]);
    }
    __syncthreads();
    for (int idx = t; idx < HC * HC; idx += 512) {
        int oy = idx >> (LGF - 1), ox = idx & (HC - 1);
        int r0 = 2 * oy;
        C[idx] = W0 * (Hs[(refl(r0 - 2, HF) << (LGF - 1)) + ox] +
                       Hs[(refl(r0 + 3, HF) << (LGF - 1)) + ox])
               + W1 * (Hs[(refl(r0 - 1, HF) << (LGF - 1)) + ox] +
                       Hs[(refl(r0 + 2, HF) << (LGF - 1)) + ox])
               + W2 * (Hs[(r0 << (LGF - 1)) + ox] + Hs[((r0 + 1) << (LGF - 1)) + ox]);
    }
    __syncthreads();
    for (int idx = t; idx < HF * HF; idx += 512) {
        int yy = idx >> LGF, xx = idx & (HF - 1);
        F[idx] = fabsf(F[idx] - C[((yy >> 1) << (LGF - 1)) + (xx >> 1)]);
    }
    __syncthreads();
    float* gd = g_d + c_off[I] + (size_t)bc * HF * HF;
    float vmn = CUDART_INF_F, vmx = -CUDART_INF_F;
    for (int idx = t; idx < HF * HF; idx += 512) {
        float a = F[idx];
        gd[idx] = a;
        vmn = fminf(vmn, a); vmx = fmaxf(vmx, a);
    }
    for (int o = 16; o; o >>= 1) {
        vmn = fminf(vmn, __shfl_xor_sync(~0u, vmn, o));
        vmx = fmaxf(vmx, __shfl_xor_sync(~0u, vmx, o));
    }
    if ((t & 31) == 0) { wmn[t >> 5] = vmn; wmx[t >> 5] = vmx; }
    if (LGF == 6) {
        if (t < 288) {  // 9 tiles of 16x16, one warp each
            int tile = t >> 5, lane = t & 31;
            int tix = tile % 3, tjy = tile / 3;
            float m = -CUDART_INF_F;
#pragma unroll
            for (int k = 0; k < 8; k++) {
                int p = lane + k * 32;
                m = fmaxf(m, F[(tjy * 16 + (p >> 4)) * 64 + tix * 16 + (p & 15)]);
            }
            for (int o = 16; o; o >>= 1) m = fmaxf(m, __shfl_xor_sync(~0u, m, o));
            if (lane == 0) stile[tile] = m;
        }
    } else if (LGF == 5) {
        if (t < 256) {  // single 16x16 tile at top-left
            float m = F[(t >> 4) * 32 + (t & 15)];
            for (int o = 16; o; o >>= 1) m = fmaxf(m, __shfl_xor_sync(~0u, m, o));
            if ((t & 31) == 0) stile[t >> 5] = m;
        }
    }
    __syncthreads();
    if (t == 0) {
        float mn = wmn[0], mx = wmx[0];
        for (int w = 1; w < 16; w++) { mn = fminf(mn, wmn[w]); mx = fmaxf(mx, wmx[w]); }
        float ts = 0.f;
        if (LGF == 6) { for (int k = 0; k < 9; k++) ts += stile[k]; }
        else if (LGF == 5) { ts = stile[0]; for (int k = 1; k < 8; k++) ts = fmaxf(ts, stile[k]); }
        g_dmn[bc * 7 + I] = fenc(mn);
        g_dmx[bc * 7 + I] = fenc(mx);
        g_tsum[bc * 7 + I] = ts;
    }
    __syncthreads();
}

// ---------------- fused mid kernel -------------------------------------------
__global__ void __launch_bounds__(512) k_mid() {
    __shared__ float A[4096], Bb[1024], Hs[2048];
    __shared__ float wmn[16], wmx[16], stile[32];
    const int bx = blockIdx.x, t = threadIdx.x;

    if (bx >= 24) {
        // ---- diff i = 0 or 1, one 32x16 region per block ----
        int bx2 = bx - 24;
        int i, bc, rx, ry, h;
        if (bx2 < 3072) { i = 0; bc = bx2 >> 7; int rg = bx2 & 127; rx = rg & 7; ry = rg >> 3; h = 256; }
        else { bx2 -= 3072; i = 1; bc = bx2 >> 5; int rg = bx2 & 31; rx = rg & 3; ry = rg >> 2; h = 128; }
        const int hc = h >> 1;
        const int gx = rx * 32 + (t & 31), gy = ry * 16 + (t >> 5);
        const float* fine   = g_pyr + c_off[i]     + (size_t)bc * h * h;
        const float* coarse = g_pyr + c_off[i + 1] + (size_t)bc * hc * hc;
        float d = fabsf(fine[gy * h + gx] - coarse[(gy >> 1) * hc + (gx >> 1)]);
        g_d[c_off[i] + (size_t)bc * h * h + gy * h + gx] = d;
        float vmn = d, vmx = d;
        for (int o = 16; o; o >>= 1) {
            vmn = fminf(vmn, __shfl_xor_sync(~0u, vmn, o));
            vmx = fmaxf(vmx, __shfl_xor_sync(~0u, vmx, o));
        }
        if ((t & 31) == 0) { wmn[t >> 5] = vmn; wmx[t >> 5] = vmx; }
        float m = d;  // 16x16 tile max: half-warp reduce
        for (int o = 8; o; o >>= 1) m = fmaxf(m, __shfl_xor_sync(~0u, m, o, 16));
        if ((t & 15) == 0) stile[((t >> 4) & 1) * 16 + (t >> 5)] = m;
        __syncthreads();
        if (t < 2) {
            float tm = stile[t * 16];
            for (int k = 1; k < 16; k++) tm = fmaxf(tm, stile[t * 16 + k]);
            int n = (16 >> i) - 1;
            int ti = rx * 2 + t, tj = ry;
            if (ti < n && tj < n) atomicAdd(&g_tsum[bc * 7 + i], tm);
        }
        if (t == 2) {
            float mn = wmn[0], mx = wmx[0];
            for (int w = 1; w < 16; w++) { mn = fminf(mn, wmn[w]); mx = fmaxf(mx, wmx[w]); }
            atomicMin(&g_dmn[bc * 7 + i], fenc(mn));
            atomicMax(&g_dmx[bc * 7 + i], fenc(mx));
        }
        return;
    }

    // ---- tail: per-(b,c) pyramid 64..2 + diffs i=2..6 in smem ----
    const int bc = bx;
    const float* src = g_pyr + c_off[2] + (size_t)bc * 4096;
    for (int idx = t; idx < 4096; idx += 512) A[idx] = src[idx];
    __syncthreads();
    tail_stage<6>(t, bc, A, Bb, Hs, wmn, wmx, stile);
    tail_stage<5>(t, bc, Bb, A, Hs, wmn, wmx, stile);
    tail_stage<4>(t, bc, A, Bb, Hs, wmn, wmx, stile);
    tail_stage<3>(t, bc, Bb, A, Hs, wmn, wmx, stile);
    tail_stage<2>(t, bc, A, Bb, Hs, wmn, wmx, stile);
}

// ---------------- combine channels -> quad-dup float4 -------------------------
__global__ void __launch_bounds__(512) k_comb() {
    __shared__ float sv[561];
    __shared__ float scs[3];
    const int bx = blockIdx.x, t = threadIdx.x;
    int i = 0;
#pragma unroll
    for (int k = 1; k < 7; k++) if (bx >= cb[k]) i = k;
    const int lg = 8 - i;
    const int h = 1 << lg;
    const int rel = bx - cb[i];
    const int lgt = (i <= 3) ? (2 * lg - 8) : 0;
    const int b = rel >> lgt;
    const int tile = rel & ((1 << lgt) - 1);
    if (t < 3) {
        float mn;
        scs[t] = calc_scale((b * 3 + t) * 7 + i, i, &mn);
    }
    __syncthreads();
    const float* dbase = g_d + c_off[i] + (size_t)(b * 3) * h * h;
    if (i <= 3) {
        const int lgtx = lg - 5;
        const int tx = tile & ((1 << lgtx) - 1), ty = tile >> lgtx;
        if (t < 297) {
            int hy = t / 33, hx = t - hy * 33;
            int x = min(tx * 32 + hx, h - 1);
            int y = min(ty * 8 + hy, h - 1);
            sv[hy * 33 + hx] = scs[0] * dbase[y * h + x]
                             + scs[1] * dbase[h * h + y * h + x]
                             + scs[2] * dbase[2 * h * h + y * h + x];
        }
        __syncthreads();
        if (t < 256) {
            int ox = t & 31, oy = t >> 5;
            float4 q = make_float4(sv[oy * 33 + ox], sv[oy * 33 + ox + 1],
                                   sv[(oy + 1) * 33 + ox], sv[(oy + 1) * 33 + ox + 1]);
            g_q[co2[i] + (size_t)b * h * h + (ty * 8 + oy) * h + tx * 32 + ox] = q;
        }
    } else {
        const int hp = h + 1;
        if (t < hp * hp) {
            int hy = t / hp, hx = t - hy * hp;
            int x = min(hx, h - 1), y = min(hy, h - 1);
            sv[hy * 33 + hx] = scs[0] * dbase[y * h + x]
                             + scs[1] * dbase[h * h + y * h + x]
                             + scs[2] * dbase[2 * h * h + y * h + x];
        }
        __syncthreads();
        if (t < h * h) {
            int ox = t & (h - 1), oy = t >> lg;
            float4 q = make_float4(sv[oy * 33 + ox], sv[oy * 33 + ox + 1],
                                   sv[(oy + 1) * 33 + ox], sv[(oy + 1) * 33 + ox + 1]);
            g_q[co2[i] + (size_t)b * h * h + oy * h + ox] = q;
        }
    }
}

// ---------------- fused final gather ------------------------------------------
__global__ void __launch_bounds__(512) k_final(float* __restrict__ out) {
    __shared__ int sr0[7];
    __shared__ float swy[7], sob;
    const int t = threadIdx.x;
    const int b = blockIdx.x >> 9;
    const int y = blockIdx.x & 511;
    if (t < 32) {
        float v = 0.f;
        if (t < 21) {
            int c = t / 7, ii = t - c * 7;
            float mn;
            float sc = calc_scale((b * 3 + c) * 7 + ii, ii, &mn);
            v = -mn * sc;
        }
        for (int o = 16; o; o >>= 1) v += __shfl_xor_sync(~0u, v, o);
        if (t == 0) sob = v;
    }
    if (t >= 32 && t < 39) {
        int ii = t - 32;
        int hh = 256 >> ii;
        float fy = fminf(fmaxf((y + 0.5f) * (float)hh * (1.f / 512.f) - 0.5f, 0.f),
                         (float)(hh - 1));
        int y0 = (int)fy;
        swy[ii] = fy - (float)y0;
        sr0[ii] = y0 * hh;
    }
    __syncthreads();
    const int x = t;
    float acc = 0.f;
#pragma unroll
    for (int i = 0; i < 7; i++) {
        const int hh = 256 >> i;
        float fx = fminf(fmaxf((x + 0.5f) * (float)hh * (1.f / 512.f) - 0.5f, 0.f),
                         (float)(hh - 1));
        int x0 = (int)fx;
        float wx = fx - (float)x0;
        float4 p = g_q[co2[i] + (size_t)b * hh * hh + sr0[i] + x0];
        float v0 = fmaf(wx, p.y - p.x, p.x);
        float v1 = fmaf(wx, p.w - p.z, p.z);
        acc += fmaf(swy[i], v1 - v0, v0);
    }
    out[((size_t)b << 18) + y * 512 + x] = acc + sob;
}

extern "C" void kernel_launch(void* const* d_in, const int* in_sizes, int n_in,
                              void* d_out, int out_size) {
    const float* x = (const float*)d_in[0];
    float* out = (float*)d_out;

    k_pyr<0><<<dim3(8, 16, 24), 512>>>(x);   // 512 -> 256 (+ stat init)
    k_pyr<1><<<dim3(4, 8, 24), 512>>>(x);    // 256 -> 128
    k_pyr<2><<<dim3(2, 4, 24), 512>>>(x);    // 128 -> 64
    k_mid<<<3864, 512>>>();                  // tail first, then diffs i=0,1
    k_comb<<<2744, 512>>>();
    k_final<<<4096, 512>>>(out);
}

// round 7
// speedup vs baseline: 1.0666x; 1.0666x over previous
#include <cuda_runtime.h>
#include <math_constants.h>

// ---------------------------------------------------------------------------
// IttiKochSaliency, x[8,3,512,512] -> out[8,512,512]
//
// 5 launches:
//  k_pyr0 : x -> L1 (256^2), separable 6-tap stride-2 reflect (+ stat init)
//  k_pd<1>: L1 -> L2 + diff0 (|L1 - up(L2)|) + stats, diff from smem halo
//  k_pd<2>: L2 -> L3 + diff1 + stats
//  k_tc   : blocks 0..7  -> per-batch tail: pyramid L3->.., diffs i=2..6,
//           stats, and quad-dup combined maps written directly (no g_d);
//           blocks 8..647 -> comb for i=0,1 (quad-dup float4 of sum_c s_c*d_c)
//  k_final: 7-level bilinear gather, 1 LDG.128 per level per pixel
//
// All diff values are >= 0, so min/max stats use raw float bit patterns
// compared as unsigned.
//
// R6 bug fixed: tail_stage had a smem race — t_tile[] was zeroed for the next
// stage in the SAME barrier interval in which threads t<3 were still reading
// it for the tile-sum stats. Reset now happens behind its own barrier.
// ---------------------------------------------------------------------------

__device__ float    g_pyr[2064384];   // levels 0..2 (h=256,128,64) per bc
__device__ float    g_d[1966080];     // diff maps i=0 (@0), i=1 (@1572864)
__device__ float4   g_q[699008];      // quad-dup combined maps per (b,i)
__device__ unsigned g_dmn[168], g_dmx[168];
__device__ float    g_tsum[168];

__constant__ int c_off[3] = {0, 1572864, 1966080};
__constant__ int co2[7]  = {0, 524288, 655360, 688128, 696320, 698368, 698880};

__device__ __forceinline__ int refl(int t, int n) {
    return t < 0 ? -t : (t >= n ? 2 * n - 2 - t : t);
}
// per-(b,c,i) affine scale (includes the 1/3 channel-mean factor)
__device__ __forceinline__ float calc_scale(int sidx, int i, float* mn_out) {
    float mn = __uint_as_float(g_dmn[sidx]);
    float mx = __uint_as_float(g_dmx[sidx]);
    float inv = 1.f / (mx - mn);
    int n = (16 >> i) - 1;
    float lm = (n > 0) ? (g_tsum[sidx] / (float)(n * n) - mn) * inv : 0.f;
    float om = 1.f - lm;
    *mn_out = mn;
    return om * om * inv * (1.f / 3.f);
}

#define W0 0.03125f
#define W1 0.15625f
#define W2 0.3125f

// ---------------- level 0 pyrdown: 512 -> 256 --------------------------------
__global__ void __launch_bounds__(512) k_pyr0(const float* __restrict__ x) {
    constexpr int HI = 512, HO = 256;
    __shared__ float s_in[36 * 68];
    __shared__ float s_h[36 * 32];
    const int t = threadIdx.x;
    if (blockIdx.x == 0 && blockIdx.y == 0 && blockIdx.z == 0 && t < 168) {
        g_dmn[t] = 0xFFFFFFFFu; g_dmx[t] = 0u; g_tsum[t] = 0.f;
    }
    const int bc = blockIdx.z;
    const int ox0 = blockIdx.x * 32, oy0 = blockIdx.y * 16;
    const float* in = x + (size_t)bc * HI * HI;
    float* out = g_pyr + (size_t)bc * HO * HO;
    const int iy0 = 2 * oy0 - 2, ix0 = 2 * ox0 - 2;
    for (int idx = t; idx < 36 * 34; idx += 512) {
        int r = idx / 34, c2 = idx - r * 34;
        int gy = refl(iy0 + r, HI);
        int ix = ix0 + 2 * c2;
        float v0, v1;
        if (ix >= 0 && ix + 2 <= HI) {
            float2 p = *(const float2*)(in + gy * HI + ix);
            v0 = p.x; v1 = p.y;
        } else {
            v0 = in[gy * HI + refl(ix, HI)];
            v1 = in[gy * HI + refl(ix + 1, HI)];
        }
        s_in[r * 68 + 2 * c2] = v0;
        s_in[r * 68 + 2 * c2 + 1] = v1;
    }
    __syncthreads();
    for (int idx = t; idx < 36 * 32; idx += 512) {
        int r = idx >> 5, c = idx & 31;
        const float* p = s_in + r * 68 + 2 * c;
        s_h[idx] = W0 * (p[0] + p[5]) + W1 * (p[1] + p[4]) + W2 * (p[2] + p[3]);
    }
    __syncthreads();
    const int tx = t & 31, ty = t >> 5;
    const float* q = s_h + 2 * ty * 32 + tx;
    float acc = W0 * (q[0] + q[160]) + W1 * (q[32] + q[128]) + W2 * (q[64] + q[96]);
    out[(oy0 + ty) * HO + ox0 + tx] = acc;
}

// ---------------- pyrdown + fused diff (LVL = 1 or 2) ------------------------
template <int LVL>
__global__ void __launch_bounds__(512) k_pd() {
    constexpr int HI = 512 >> LVL, HO = HI / 2;
    constexpr int I = LVL - 1;          // diff map index
    constexpr int NT = (16 >> I) - 1;   // counted tile grid (15 or 7)
    __shared__ float s_in[36 * 68];
    __shared__ float s_h[36 * 32];
    __shared__ float sout[16 * 32];
    __shared__ unsigned s_mn, s_mx, stile[8];
    const int t = threadIdx.x;
    if (t == 0) { s_mn = 0xFFFFFFFFu; s_mx = 0u; }
    if (t < 8) stile[t] = 0u;
    const int bc = blockIdx.z;
    const int ox0 = blockIdx.x * 32, oy0 = blockIdx.y * 16;
    const float* in = g_pyr + c_off[LVL - 1] + (size_t)bc * HI * HI;
    float* outp = g_pyr + c_off[LVL] + (size_t)bc * HO * HO;
    const int iy0 = 2 * oy0 - 2, ix0 = 2 * ox0 - 2;
    for (int idx = t; idx < 36 * 34; idx += 512) {
        int r = idx / 34, c2 = idx - r * 34;
        int gy = refl(iy0 + r, HI);
        int ix = ix0 + 2 * c2;
        float v0, v1;
        if (ix >= 0 && ix + 2 <= HI) {
            float2 p = *(const float2*)(in + gy * HI + ix);
            v0 = p.x; v1 = p.y;
        } else {
            v0 = in[gy * HI + refl(ix, HI)];
            v1 = in[gy * HI + refl(ix + 1, HI)];
        }
        s_in[r * 68 + 2 * c2] = v0;
        s_in[r * 68 + 2 * c2 + 1] = v1;
    }
    __syncthreads();
    for (int idx = t; idx < 36 * 32; idx += 512) {
        int r = idx >> 5, c = idx & 31;
        const float* p = s_in + r * 68 + 2 * c;
        s_h[idx] = W0 * (p[0] + p[5]) + W1 * (p[1] + p[4]) + W2 * (p[2] + p[3]);
    }
    __syncthreads();
    {
        const int tx = t & 31, ty = t >> 5;
        const float* q = s_h + 2 * ty * 32 + tx;
        float acc = W0 * (q[0] + q[160]) + W1 * (q[32] + q[128]) + W2 * (q[64] + q[96]);
        outp[(oy0 + ty) * HO + ox0 + tx] = acc;
        sout[ty * 32 + tx] = acc;
    }
    __syncthreads();
    // diff for the 64x32 fine region at (2ox0, 2oy0): fine values live in s_in
    {
        const int p = t * 4;
        const int ly = p >> 6, lx = p & 63;
        const float* fr = s_in + (ly + 2) * 68 + lx + 2;
        const float c0 = sout[(ly >> 1) * 32 + (lx >> 1)];
        const float c1 = sout[(ly >> 1) * 32 + (lx >> 1) + 1];
        float d0 = fabsf(fr[0] - c0), d1 = fabsf(fr[1] - c0);
        float d2 = fabsf(fr[2] - c1), d3 = fabsf(fr[3] - c1);
        float* gd = g_d + (I ? 1572864 : 0) + (size_t)bc * HI * HI;
        *(float4*)(gd + (2 * oy0 + ly) * HI + 2 * ox0 + lx) = make_float4(d0, d1, d2, d3);
        float mx4 = fmaxf(fmaxf(d0, d1), fmaxf(d2, d3));
        float mn4 = fminf(fminf(d0, d1), fminf(d2, d3));
        float tm = mx4;  // 16x16 tile max: 4 consecutive lanes share a tile
        tm = fmaxf(tm, __shfl_xor_sync(~0u, tm, 1, 4));
        tm = fmaxf(tm, __shfl_xor_sync(~0u, tm, 2, 4));
        if ((t & 3) == 0)
            atomicMax(&stile[(ly >> 4) * 4 + (lx >> 4)], __float_as_uint(tm));
        for (int o = 16; o; o >>= 1) {
            mx4 = fmaxf(mx4, __shfl_xor_sync(~0u, mx4, o));
            mn4 = fminf(mn4, __shfl_xor_sync(~0u, mn4, o));
        }
        if ((t & 31) == 0) {
            atomicMax(&s_mx, __float_as_uint(mx4));
            atomicMin(&s_mn, __float_as_uint(mn4));
        }
    }
    __syncthreads();
    const int sidx = bc * 7 + I;
    if (t == 0) { atomicMin(&g_dmn[sidx], s_mn); atomicMax(&g_dmx[sidx], s_mx); }
    if (t < 8) {
        int gtc = 4 * blockIdx.x + (t & 3);
        int gtr = 2 * blockIdx.y + (t >> 2);
        if (gtc < NT && gtr < NT)
            atomicAdd(&g_tsum[sidx], __uint_as_float(stile[t]));
    }
}

// ---------------- one tail stage (compile-time size), 3 channels in parallel --
template <int LGF>
__device__ __forceinline__ void tail_stage(int t, int b, float* Fb, int FS,
                                           float* Cb, int CS, float* H,
                                           unsigned* t_mn, unsigned* t_mx,
                                           unsigned* t_tile, float* t_s) {
    constexpr int HF = 1 << LGF, HC = HF >> 1, I = 8 - LGF;
    for (int idx = t; idx < 3 * HF * HC; idx += 512) {
        int c = idx / (HF * HC);
        int rem = idx - c * (HF * HC);
        int r = rem >> (LGF - 1);
        const float* row = Fb + c * FS + (r << LGF);
        int c0 = 2 * (rem & (HC - 1));
        H[c * 2048 + rem] = W0 * (row[refl(c0 - 2, HF)] + row[refl(c0 + 3, HF)])
                          + W1 * (row[refl(c0 - 1, HF)] + row[refl(c0 + 2, HF)])
                          + W2 * (row[c0] + row[c0 + 1]);
    }
    __syncthreads();
    for (int idx = t; idx < 3 * HC * HC; idx += 512) {
        int c = idx / (HC * HC);
        int rem = idx - c * (HC * HC);
        int oy = rem >> (LGF - 1), ox = rem & (HC - 1);
        const float* hb = H + c * 2048;
        int r0 = 2 * oy;
        float cv = W0 * (hb[(refl(r0 - 2, HF) << (LGF - 1)) + ox] +
                         hb[(refl(r0 + 3, HF) << (LGF - 1)) + ox])
                 + W1 * (hb[(refl(r0 - 1, HF) << (LGF - 1)) + ox] +
                         hb[(refl(r0 + 2, HF) << (LGF - 1)) + ox])
                 + W2 * (hb[(r0 << (LGF - 1)) + ox] + hb[((r0 + 1) << (LGF - 1)) + ox]);
        Cb[c * CS + rem] = cv;
        float* A = Fb + c * FS;
        int f0 = (oy << (LGF + 1)) + 2 * ox;
        float d00 = fabsf(A[f0] - cv),      d01 = fabsf(A[f0 + 1] - cv);
        float d10 = fabsf(A[f0 + HF] - cv), d11 = fabsf(A[f0 + HF + 1] - cv);
        A[f0] = d00; A[f0 + 1] = d01; A[f0 + HF] = d10; A[f0 + HF + 1] = d11;
        float mx4 = fmaxf(fmaxf(d00, d01), fmaxf(d10, d11));
        float mn4 = fminf(fminf(d00, d01), fminf(d10, d11));
        if (LGF >= 4) {  // totals are multiples of 32 -> full warps active
            float a = mx4, n2 = mn4;
            for (int o = 16; o; o >>= 1) {
                a = fmaxf(a, __shfl_xor_sync(~0u, a, o));
                n2 = fminf(n2, __shfl_xor_sync(~0u, n2, o));
            }
            if ((t & 31) == 0) {
                atomicMax(&t_mx[c], __float_as_uint(a));
                atomicMin(&t_mn[c], __float_as_uint(n2));
            }
        } else {
            atomicMax(&t_mx[c], __float_as_uint(mx4));
            atomicMin(&t_mn[c], __float_as_uint(mn4));
        }
        if (LGF == 6)
            atomicMax(&t_tile[c * 16 + (oy >> 3) * 4 + (ox >> 3)], __float_as_uint(mx4));
        else if (LGF == 5) {
            if (oy < 8 && ox < 8) atomicMax(&t_tile[c * 16], __float_as_uint(mx4));
        }
    }
    __syncthreads();
    if (t < 3) {
        float mn = __uint_as_float(t_mn[t]), mx = __uint_as_float(t_mx[t]);
        float ts = 0.f;
        if (LGF == 6) {
            for (int k = 0; k < 3; k++)
                for (int j = 0; j < 3; j++) ts += __uint_as_float(t_tile[t * 16 + k * 4 + j]);
        } else if (LGF == 5) ts = __uint_as_float(t_tile[t * 16]);
        int sidx = (b * 3 + t) * 7 + I;
        g_dmn[sidx] = __float_as_uint(mn);
        g_dmx[sidx] = __float_as_uint(mx);
        g_tsum[sidx] = ts;
        float inv = 1.f / (mx - mn);
        constexpr int NTT = (LGF == 6) ? 3 : (LGF == 5 ? 1 : 0);
        float lm = (NTT > 0) ? (ts / (float)(NTT * NTT) - mn) * inv : 0.f;
        float om = 1.f - lm;
        t_s[t] = om * om * inv * (1.f / 3.f);
    }
    __syncthreads();   // FIX: stats fully read before resetting for next stage
    if (t < 48) t_tile[t] = 0u;
    if (t >= 64 && t < 67) { t_mn[t - 64] = 0xFFFFFFFFu; t_mx[t - 64] = 0u; }
    __syncthreads();
    // comb: quad-dup combined map written straight to g_q
    for (int idx = t; idx < HF * HF; idx += 512) {
        int y = idx >> LGF, x = idx & (HF - 1);
        int x1 = min(x + 1, HF - 1), y1 = min(y + 1, HF - 1);
        float4 q = make_float4(0.f, 0.f, 0.f, 0.f);
#pragma unroll
        for (int c = 0; c < 3; c++) {
            const float* A = Fb + c * FS;
            float s = t_s[c];
            q.x = fmaf(A[(y << LGF) + x], s, q.x);
            q.y = fmaf(A[(y << LGF) + x1], s, q.y);
            q.z = fmaf(A[(y1 << LGF) + x], s, q.z);
            q.w = fmaf(A[(y1 << LGF) + x1], s, q.w);
        }
        g_q[co2[I] + b * HF * HF + idx] = q;
    }
    __syncthreads();
}

// ---------------- tail (blocks 0..7) + comb i=0,1 (blocks 8..647) ------------
__global__ void __launch_bounds__(512) k_tc() {
    extern __shared__ float sm[];
    const int t = threadIdx.x;
    const int bx = blockIdx.x;
    if (bx < 8) {
        float* F0 = sm;            // 3 * 4096
        float* F1 = sm + 12288;    // 3 * 1024
        float* H  = sm + 15360;    // 3 * 2048
        __shared__ unsigned t_mn[3], t_mx[3], t_tile[48];
        __shared__ float t_s[3];
        if (t < 3) { t_mn[t] = 0xFFFFFFFFu; t_mx[t] = 0u; }
        if (t < 48) t_tile[t] = 0u;
        const int b = bx;
        const float* src = g_pyr + c_off[2] + (size_t)(b * 3) * 4096;
        for (int idx = t; idx < 12288; idx += 512) F0[idx] = src[idx];
        __syncthreads();
        tail_stage<6>(t, b, F0, 4096, F1, 1024, H, t_mn, t_mx, t_tile, t_s);
        tail_stage<5>(t, b, F1, 1024, F0, 4096, H, t_mn, t_mx, t_tile, t_s);
        tail_stage<4>(t, b, F0, 4096, F1, 1024, H, t_mn, t_mx, t_tile, t_s);
        tail_stage<3>(t, b, F1, 1024, F0, 4096, H, t_mn, t_mx, t_tile, t_s);
        tail_stage<2>(t, b, F0, 4096, F1, 1024, H, t_mn, t_mx, t_tile, t_s);
        return;
    }
    // ---- comb for i=0,1: quad-region 64x16 per block ----
    __shared__ float scs[3];
    int rb = bx - 8;
    int i, b, tile;
    if (rb < 512) { i = 0; b = rb >> 6; tile = rb & 63; }
    else { rb -= 512; i = 1; b = rb >> 4; tile = rb & 15; }
    const int h = 256 >> i;
    const int tx = (i == 0) ? (tile & 3) : (tile & 1);
    const int ty = (i == 0) ? (tile >> 2) : (tile >> 1);
    float* sv = sm;  // 17 x 66
    if (t < 3) { float mn; scs[t] = calc_scale((b * 3 + t) * 7 + i, i, &mn); }
    __syncthreads();
    const float* db = g_d + (i ? 1572864 : 0) + (size_t)(b * 3) * h * h;
    const int x0 = tx * 64, y0 = ty * 16;
    for (int idx = t; idx < 17 * 65; idx += 512) {
        int yy = idx / 65, xx = idx - yy * 65;
        int gx = min(x0 + xx, h - 1), gy = min(y0 + yy, h - 1);
        const float* p = db + gy * h + gx;
        sv[yy * 66 + xx] = scs[0] * p[0] + scs[1] * p[h * h] + scs[2] * p[2 * h * h];
    }
    __syncthreads();
    for (int idx = t; idx < 1024; idx += 512) {
        int oy = idx >> 6, ox = idx & 63;
        float4 q = make_float4(sv[oy * 66 + ox], sv[oy * 66 + ox + 1],
                               sv[(oy + 1) * 66 + ox], sv[(oy + 1) * 66 + ox + 1]);
        g_q[co2[i] + b * h * h + (y0 + oy) * h + x0 + ox] = q;
    }
}

// ---------------- fused final gather -----------------------------------------
__global__ void __launch_bounds__(512) k_final(float* __restrict__ out) {
    __shared__ int sr0[7];
    __shared__ float swy[7], sob;
    const int t = threadIdx.x;
    const int b = blockIdx.x >> 9;
    const int y = blockIdx.x & 511;
    if (t < 32) {
        float v = 0.f;
        if (t < 21) {
            int c = t / 7, ii = t - c * 7;
            float mn;
            float sc = calc_scale((b * 3 + c) * 7 + ii, ii, &mn);
            v = -mn * sc;
        }
        for (int o = 16; o; o >>= 1) v += __shfl_xor_sync(~0u, v, o);
        if (t == 0) sob = v;
    }
    if (t >= 32 && t < 39) {
        int ii = t - 32;
        int hh = 256 >> ii;
        float fy = fminf(fmaxf((y + 0.5f) * (float)hh * (1.f / 512.f) - 0.5f, 0.f),
                         (float)(hh - 1));
        int y0 = (int)fy;
        swy[ii] = fy - (float)y0;
        sr0[ii] = y0 * hh;
    }
    __syncthreads();
    const int x = t;
    float acc = 0.f;
#pragma unroll
    for (int i = 0; i < 7; i++) {
        const int hh = 256 >> i;
        float fx = fminf(fmaxf((x + 0.5f) * (float)hh * (1.f / 512.f) - 0.5f, 0.f),
                         (float)(hh - 1));
        int x0 = (int)fx;
        float wx = fx - (float)x0;
        float4 p = g_q[co2[i] + (size_t)b * hh * hh + sr0[i] + x0];
        float v0 = fmaf(wx, p.y - p.x, p.x);
        float v1 = fmaf(wx, p.w - p.z, p.z);
        acc += fmaf(swy[i], v1 - v0, v0);
    }
    out[((size_t)b << 18) + y * 512 + x] = acc + sob;
}

extern "C" void kernel_launch(void* const* d_in, const int* in_sizes, int n_in,
                              void* d_out, int out_size) {
    const float* x = (const float*)d_in[0];
    float* out = (float*)d_out;

    cudaFuncSetAttribute(k_tc, cudaFuncAttributeMaxDynamicSharedMemorySize, 86016);

    k_pyr0<<<dim3(8, 16, 24), 512>>>(x);   // 512 -> 256 (+ stat init)
    k_pd<1><<<dim3(4, 8, 24), 512>>>();    // 256 -> 128 + diff0 + stats
    k_pd<2><<<dim3(2, 4, 24), 512>>>();    // 128 -> 64  + diff1 + stats
    k_tc<<<648, 512, 86016>>>();           // tail (8 blocks) + comb i=0,1
    k_final<<<4096, 512>>>(out);
}

// round 8
// speedup vs baseline: 1.1037x; 1.0347x over previous
#include <cuda_runtime.h>
#include <math_constants.h>

// ---------------------------------------------------------------------------
// IttiKochSaliency, x[8,3,512,512] -> out[8,512,512]
//
// 5 launches:
//  k_pyr0 : x -> L1 (256^2), separable 6-tap stride-2 reflect (+ stat init)
//  k_pd<1>: L1 -> L2 + diff0 (|L1 - up(L2)|) + stats, diff from smem halo
//  k_pd<2>: L2 -> L3 + diff1 + stats
//  k_tc   : 1024 threads. blocks 0..7: per-batch tail (pyramid L3->.., diffs
//           i=2..6, stats, quad-dup comb maps written directly);
//           blocks 8..199: comb i=0,1 as full-width 16-row strips (one wave)
//  k_final: 1024 threads, 2 output rows per block; 7 LDG.128 per pixel
// ---------------------------------------------------------------------------

__device__ float    g_pyr[2064384];   // levels 0..2 (h=256,128,64) per bc
__device__ float    g_d[1966080];     // diff maps i=0 (@0), i=1 (@1572864)
__device__ float4   g_q[699008];      // quad-dup combined maps per (b,i)
__device__ unsigned g_dmn[168], g_dmx[168];
__device__ float    g_tsum[168];

__constant__ int c_off[3] = {0, 1572864, 1966080};
__constant__ int co2[7]  = {0, 524288, 655360, 688128, 696320, 698368, 698880};

__device__ __forceinline__ int refl(int t, int n) {
    return t < 0 ? -t : (t >= n ? 2 * n - 2 - t : t);
}
// per-(b,c,i) affine scale (includes the 1/3 channel-mean factor)
__device__ __forceinline__ float calc_scale(int sidx, int i, float* mn_out) {
    float mn = __uint_as_float(g_dmn[sidx]);
    float mx = __uint_as_float(g_dmx[sidx]);
    float inv = 1.f / (mx - mn);
    int n = (16 >> i) - 1;
    float lm = (n > 0) ? (g_tsum[sidx] / (float)(n * n) - mn) * inv : 0.f;
    float om = 1.f - lm;
    *mn_out = mn;
    return om * om * inv * (1.f / 3.f);
}

#define W0 0.03125f
#define W1 0.15625f
#define W2 0.3125f

// ---------------- level 0 pyrdown: 512 -> 256 --------------------------------
__global__ void __launch_bounds__(512) k_pyr0(const float* __restrict__ x) {
    constexpr int HI = 512, HO = 256;
    __shared__ float s_in[36 * 68];
    __shared__ float s_h[36 * 32];
    const int t = threadIdx.x;
    if (blockIdx.x == 0 && blockIdx.y == 0 && blockIdx.z == 0 && t < 168) {
        g_dmn[t] = 0xFFFFFFFFu; g_dmx[t] = 0u; g_tsum[t] = 0.f;
    }
    const int bc = blockIdx.z;
    const int ox0 = blockIdx.x * 32, oy0 = blockIdx.y * 16;
    const float* in = x + (size_t)bc * HI * HI;
    float* out = g_pyr + (size_t)bc * HO * HO;
    const int iy0 = 2 * oy0 - 2, ix0 = 2 * ox0 - 2;
    for (int idx = t; idx < 36 * 34; idx += 512) {
        int r = idx / 34, c2 = idx - r * 34;
        int gy = refl(iy0 + r, HI);
        int ix = ix0 + 2 * c2;
        float v0, v1;
        if (ix >= 0 && ix + 2 <= HI) {
            float2 p = *(const float2*)(in + gy * HI + ix);
            v0 = p.x; v1 = p.y;
        } else {
            v0 = in[gy * HI + refl(ix, HI)];
            v1 = in[gy * HI + refl(ix + 1, HI)];
        }
        s_in[r * 68 + 2 * c2] = v0;
        s_in[r * 68 + 2 * c2 + 1] = v1;
    }
    __syncthreads();
    for (int idx = t; idx < 36 * 32; idx += 512) {
        int r = idx >> 5, c = idx & 31;
        const float* p = s_in + r * 68 + 2 * c;
        s_h[idx] = W0 * (p[0] + p[5]) + W1 * (p[1] + p[4]) + W2 * (p[2] + p[3]);
    }
    __syncthreads();
    const int tx = t & 31, ty = t >> 5;
    const float* q = s_h + 2 * ty * 32 + tx;
    float acc = W0 * (q[0] + q[160]) + W1 * (q[32] + q[128]) + W2 * (q[64] + q[96]);
    out[(oy0 + ty) * HO + ox0 + tx] = acc;
}

// ---------------- pyrdown + fused diff (LVL = 1 or 2) ------------------------
template <int LVL>
__global__ void __launch_bounds__(512) k_pd() {
    constexpr int HI = 512 >> LVL, HO = HI / 2;
    constexpr int I = LVL - 1;          // diff map index
    constexpr int NT = (16 >> I) - 1;   // counted tile grid (15 or 7)
    __shared__ float s_in[36 * 68];
    __shared__ float s_h[36 * 32];
    __shared__ float sout[16 * 32];
    __shared__ unsigned s_mn, s_mx, stile[8];
    const int t = threadIdx.x;
    if (t == 0) { s_mn = 0xFFFFFFFFu; s_mx = 0u; }
    if (t < 8) stile[t] = 0u;
    const int bc = blockIdx.z;
    const int ox0 = blockIdx.x * 32, oy0 = blockIdx.y * 16;
    const float* in = g_pyr + c_off[LVL - 1] + (size_t)bc * HI * HI;
    float* outp = g_pyr + c_off[LVL] + (size_t)bc * HO * HO;
    const int iy0 = 2 * oy0 - 2, ix0 = 2 * ox0 - 2;
    for (int idx = t; idx < 36 * 34; idx += 512) {
        int r = idx / 34, c2 = idx - r * 34;
        int gy = refl(iy0 + r, HI);
        int ix = ix0 + 2 * c2;
        float v0, v1;
        if (ix >= 0 && ix + 2 <= HI) {
            float2 p = *(const float2*)(in + gy * HI + ix);
            v0 = p.x; v1 = p.y;
        } else {
            v0 = in[gy * HI + refl(ix, HI)];
            v1 = in[gy * HI + refl(ix + 1, HI)];
        }
        s_in[r * 68 + 2 * c2] = v0;
        s_in[r * 68 + 2 * c2 + 1] = v1;
    }
    __syncthreads();
    for (int idx = t; idx < 36 * 32; idx += 512) {
        int r = idx >> 5, c = idx & 31;
        const float* p = s_in + r * 68 + 2 * c;
        s_h[idx] = W0 * (p[0] + p[5]) + W1 * (p[1] + p[4]) + W2 * (p[2] + p[3]);
    }
    __syncthreads();
    {
        const int tx = t & 31, ty = t >> 5;
        const float* q = s_h + 2 * ty * 32 + tx;
        float acc = W0 * (q[0] + q[160]) + W1 * (q[32] + q[128]) + W2 * (q[64] + q[96]);
        outp[(oy0 + ty) * HO + ox0 + tx] = acc;
        sout[ty * 32 + tx] = acc;
    }
    __syncthreads();
    // diff for the 64x32 fine region at (2ox0, 2oy0): fine values live in s_in
    {
        const int p = t * 4;
        const int ly = p >> 6, lx = p & 63;
        const float* fr = s_in + (ly + 2) * 68 + lx + 2;
        const float c0 = sout[(ly >> 1) * 32 + (lx >> 1)];
        const float c1 = sout[(ly >> 1) * 32 + (lx >> 1) + 1];
        float d0 = fabsf(fr[0] - c0), d1 = fabsf(fr[1] - c0);
        float d2 = fabsf(fr[2] - c1), d3 = fabsf(fr[3] - c1);
        float* gd = g_d + (I ? 1572864 : 0) + (size_t)bc * HI * HI;
        *(float4*)(gd + (2 * oy0 + ly) * HI + 2 * ox0 + lx) = make_float4(d0, d1, d2, d3);
        float mx4 = fmaxf(fmaxf(d0, d1), fmaxf(d2, d3));
        float mn4 = fminf(fminf(d0, d1), fminf(d2, d3));
        float tm = mx4;  // 16x16 tile max: 4 consecutive lanes share a tile
        tm = fmaxf(tm, __shfl_xor_sync(~0u, tm, 1, 4));
        tm = fmaxf(tm, __shfl_xor_sync(~0u, tm, 2, 4));
        if ((t & 3) == 0)
            atomicMax(&stile[(ly >> 4) * 4 + (lx >> 4)], __float_as_uint(tm));
        for (int o = 16; o; o >>= 1) {
            mx4 = fmaxf(mx4, __shfl_xor_sync(~0u, mx4, o));
            mn4 = fminf(mn4, __shfl_xor_sync(~0u, mn4, o));
        }
        if ((t & 31) == 0) {
            atomicMax(&s_mx, __float_as_uint(mx4));
            atomicMin(&s_mn, __float_as_uint(mn4));
        }
    }
    __syncthreads();
    const int sidx = bc * 7 + I;
    if (t == 0) { atomicMin(&g_dmn[sidx], s_mn); atomicMax(&g_dmx[sidx], s_mx); }
    if (t < 8) {
        int gtc = 4 * blockIdx.x + (t & 3);
        int gtr = 2 * blockIdx.y + (t >> 2);
        if (gtc < NT && gtr < NT)
            atomicAdd(&g_tsum[sidx], __uint_as_float(stile[t]));
    }
}

// ---------------- one tail stage (compile-time size), 3 channels in parallel --
template <int LGF>
__device__ __forceinline__ void tail_stage(int t, int b, float* Fb, int FS,
                                           float* Cb, int CS, float* H,
                                           unsigned* t_mn, unsigned* t_mx,
                                           unsigned* t_tile, float* t_s) {
    constexpr int HF = 1 << LGF, HC = HF >> 1, I = 8 - LGF;
    for (int idx = t; idx < 3 * HF * HC; idx += 1024) {
        int c = idx / (HF * HC);
        int rem = idx - c * (HF * HC);
        int r = rem >> (LGF - 1);
        const float* row = Fb + c * FS + (r << LGF);
        int c0 = 2 * (rem & (HC - 1));
        H[c * 2048 + rem] = W0 * (row[refl(c0 - 2, HF)] + row[refl(c0 + 3, HF)])
                          + W1 * (row[refl(c0 - 1, HF)] + row[refl(c0 + 2, HF)])
                          + W2 * (row[c0] + row[c0 + 1]);
    }
    __syncthreads();
    for (int idx = t; idx < 3 * HC * HC; idx += 1024) {
        int c = idx / (HC * HC);
        int rem = idx - c * (HC * HC);
        int oy = rem >> (LGF - 1), ox = rem & (HC - 1);
        const float* hb = H + c * 2048;
        int r0 = 2 * oy;
        float cv = W0 * (hb[(refl(r0 - 2, HF) << (LGF - 1)) + ox] +
                         hb[(refl(r0 + 3, HF) << (LGF - 1)) + ox])
                 + W1 * (hb[(refl(r0 - 1, HF) << (LGF - 1)) + ox] +
                         hb[(refl(r0 + 2, HF) << (LGF - 1)) + ox])
                 + W2 * (hb[(r0 << (LGF - 1)) + ox] + hb[((r0 + 1) << (LGF - 1)) + ox]);
        Cb[c * CS + rem] = cv;
        float* A = Fb + c * FS;
        int f0 = (oy << (LGF + 1)) + 2 * ox;
        float d00 = fabsf(A[f0] - cv),      d01 = fabsf(A[f0 + 1] - cv);
        float d10 = fabsf(A[f0 + HF] - cv), d11 = fabsf(A[f0 + HF + 1] - cv);
        A[f0] = d00; A[f0 + 1] = d01; A[f0 + HF] = d10; A[f0 + HF + 1] = d11;
        float mx4 = fmaxf(fmaxf(d00, d01), fmaxf(d10, d11));
        float mn4 = fminf(fminf(d00, d01), fminf(d10, d11));
        if (LGF >= 4) {  // totals are multiples of 32 -> participating warps full
            float a = mx4, n2 = mn4;
            for (int o = 16; o; o >>= 1) {
                a = fmaxf(a, __shfl_xor_sync(~0u, a, o));
                n2 = fminf(n2, __shfl_xor_sync(~0u, n2, o));
            }
            if ((t & 31) == 0) {
                atomicMax(&t_mx[c], __float_as_uint(a));
                atomicMin(&t_mn[c], __float_as_uint(n2));
            }
        } else {
            atomicMax(&t_mx[c], __float_as_uint(mx4));
            atomicMin(&t_mn[c], __float_as_uint(mn4));
        }
        if (LGF == 6)
            atomicMax(&t_tile[c * 16 + (oy >> 3) * 4 + (ox >> 3)], __float_as_uint(mx4));
        else if (LGF == 5) {
            if (oy < 8 && ox < 8) atomicMax(&t_tile[c * 16], __float_as_uint(mx4));
        }
    }
    __syncthreads();
    if (t < 3) {
        float mn = __uint_as_float(t_mn[t]), mx = __uint_as_float(t_mx[t]);
        float ts = 0.f;
        if (LGF == 6) {
            for (int k = 0; k < 3; k++)
                for (int j = 0; j < 3; j++) ts += __uint_as_float(t_tile[t * 16 + k * 4 + j]);
        } else if (LGF == 5) ts = __uint_as_float(t_tile[t * 16]);
        int sidx = (b * 3 + t) * 7 + I;
        g_dmn[sidx] = __float_as_uint(mn);
        g_dmx[sidx] = __float_as_uint(mx);
        g_tsum[sidx] = ts;
        float inv = 1.f / (mx - mn);
        constexpr int NTT = (LGF == 6) ? 3 : (LGF == 5 ? 1 : 0);
        float lm = (NTT > 0) ? (ts / (float)(NTT * NTT) - mn) * inv : 0.f;
        float om = 1.f - lm;
        t_s[t] = om * om * inv * (1.f / 3.f);
    }
    __syncthreads();   // stats fully read before resetting for next stage
    if (t < 48) t_tile[t] = 0u;
    if (t >= 64 && t < 67) { t_mn[t - 64] = 0xFFFFFFFFu; t_mx[t - 64] = 0u; }
    __syncthreads();
    // comb: quad-dup combined map written straight to g_q
    for (int idx = t; idx < HF * HF; idx += 1024) {
        int y = idx >> LGF, x = idx & (HF - 1);
        int x1 = min(x + 1, HF - 1), y1 = min(y + 1, HF - 1);
        float4 q = make_float4(0.f, 0.f, 0.f, 0.f);
#pragma unroll
        for (int c = 0; c < 3; c++) {
            const float* A = Fb + c * FS;
            float s = t_s[c];
            q.x = fmaf(A[(y << LGF) + x], s, q.x);
            q.y = fmaf(A[(y << LGF) + x1], s, q.y);
            q.z = fmaf(A[(y1 << LGF) + x], s, q.z);
            q.w = fmaf(A[(y1 << LGF) + x1], s, q.w);
        }
        g_q[co2[I] + b * HF * HF + idx] = q;
    }
    __syncthreads();
}

// ---------------- tail (blocks 0..7) + comb i=0,1 (blocks 8..199) ------------
__global__ void __launch_bounds__(1024) k_tc() {
    extern __shared__ float sm[];
    const int t = threadIdx.x;
    const int bx = blockIdx.x;
    if (bx < 8) {
        float* F0 = sm;            // 3 * 4096
        float* F1 = sm + 12288;    // 3 * 1024
        float* H  = sm + 15360;    // 3 * 2048
        __shared__ unsigned t_mn[3], t_mx[3], t_tile[48];
        __shared__ float t_s[3];
        if (t < 3) { t_mn[t] = 0xFFFFFFFFu; t_mx[t] = 0u; }
        if (t < 48) t_tile[t] = 0u;
        const int b = bx;
        const float4* src = (const float4*)(g_pyr + c_off[2] + (size_t)(b * 3) * 4096);
        float4* F4 = (float4*)F0;
        for (int idx = t; idx < 3072; idx += 1024) F4[idx] = src[idx];
        __syncthreads();
        tail_stage<6>(t, b, F0, 4096, F1, 1024, H, t_mn, t_mx, t_tile, t_s);
        tail_stage<5>(t, b, F1, 1024, F0, 4096, H, t_mn, t_mx, t_tile, t_s);
        tail_stage<4>(t, b, F0, 4096, F1, 1024, H, t_mn, t_mx, t_tile, t_s);
        tail_stage<3>(t, b, F1, 1024, F0, 4096, H, t_mn, t_mx, t_tile, t_s);
        tail_stage<2>(t, b, F0, 4096, F1, 1024, H, t_mn, t_mx, t_tile, t_s);
        return;
    }
    // ---- comb for i=0,1: full-width 16-row strip per block ----
    __shared__ float scs[3];
    int i, b, y0, lg;
    if (bx < 136) { int rel = bx - 8;  i = 0; b = rel >> 4; y0 = (rel & 15) * 16; lg = 8; }
    else          { int rel = bx - 136; i = 1; b = rel >> 3; y0 = (rel & 7) * 16;  lg = 7; }
    const int h = 1 << lg;
    const int S = h + 2;     // smem row stride
    const int W = h + 1;     // loaded columns (x halo)
    float* sv = sm;          // [17][S]
    if (t < 3) { float mn; scs[t] = calc_scale((b * 3 + t) * 7 + i, i, &mn); }
    __syncthreads();
    const float* db = g_d + (i ? 1572864 : 0) + (size_t)(b * 3) * h * h;
    for (int idx = t; idx < 17 * W; idx += 1024) {
        int yy = idx / W, xx = idx - yy * W;
        int gx = min(xx, h - 1), gy = min(y0 + yy, h - 1);
        const float* p = db + gy * h + gx;
        sv[yy * S + xx] = scs[0] * p[0] + scs[1] * p[h * h] + scs[2] * p[2 * h * h];
    }
    __syncthreads();
    for (int idx = t; idx < (h << 4); idx += 1024) {
        int oy = idx >> lg, ox = idx & (h - 1);
        float4 q = make_float4(sv[oy * S + ox], sv[oy * S + ox + 1],
                               sv[(oy + 1) * S + ox], sv[(oy + 1) * S + ox + 1]);
        g_q[co2[i] + b * h * h + (y0 + oy) * h + ox] = q;
    }
}

// ---------------- fused final gather: 2 rows per block ------------------------
__global__ void __launch_bounds__(1024) k_final(float* __restrict__ out) {
    __shared__ int sr0[2][7];
    __shared__ float swy[2][7], sob;
    const int t = threadIdx.x;
    const int b = blockIdx.x >> 8;
    const int yp = blockIdx.x & 255;          // row pair
    if (t < 32) {
        float v = 0.f;
        if (t < 21) {
            int c = t / 7, ii = t - c * 7;
            float mn;
            float sc = calc_scale((b * 3 + c) * 7 + ii, ii, &mn);
            v = -mn * sc;
        }
        for (int o = 16; o; o >>= 1) v += __shfl_xor_sync(~0u, v, o);
        if (t == 0) sob = v;
    }
    if (t >= 64 && t < 78) {
        int k = t - 64;
        int r = k / 7, ii = k - r * 7;
        int hh = 256 >> ii;
        int yy = 2 * yp + r;
        float fy = fminf(fmaxf((yy + 0.5f) * (float)hh * (1.f / 512.f) - 0.5f, 0.f),
                         (float)(hh - 1));
        int y0 = (int)fy;
        swy[r][ii] = fy - (float)y0;
        sr0[r][ii] = y0 * hh;
    }
    __syncthreads();
    const int r = t >> 9;
    const int x = t & 511;
    const int y = 2 * yp + r;
    float acc = 0.f;
#pragma unroll
    for (int i = 0; i < 7; i++) {
        const int hh = 256 >> i;
        float fx = fminf(fmaxf((x + 0.5f) * (float)hh * (1.f / 512.f) - 0.5f, 0.f),
                         (float)(hh - 1));
        int x0 = (int)fx;
        float wx = fx - (float)x0;
        float4 p = g_q[co2[i] + (size_t)b * hh * hh + sr0[r][i] + x0];
        float v0 = fmaf(wx, p.y - p.x, p.x);
        float v1 = fmaf(wx, p.w - p.z, p.z);
        acc += fmaf(swy[r][i], v1 - v0, v0);
    }
    out[((size_t)b << 18) + y * 512 + x] = acc + sob;
}

extern "C" void kernel_launch(void* const* d_in, const int* in_sizes, int n_in,
                              void* d_out, int out_size) {
    const float* x = (const float*)d_in[0];
    float* out = (float*)d_out;

    cudaFuncSetAttribute(k_tc, cudaFuncAttributeMaxDynamicSharedMemorySize, 86016);

    k_pyr0<<<dim3(8, 16, 24), 512>>>(x);   // 512 -> 256 (+ stat init)
    k_pd<1><<<dim3(4, 8, 24), 512>>>();    // 256 -> 128 + diff0 + stats
    k_pd<2><<<dim3(2, 4, 24), 512>>>();    // 128 -> 64  + diff1 + stats
    k_tc<<<200, 1024, 86016>>>();          // tail (8 blocks) + comb strips
    k_final<<<2048, 1024>>>(out);
}